// round 4
// baseline (speedup 1.0000x reference)
#include <cuda_runtime.h>
#include <math.h>

#define B_  32
#define HH  128
#define WW  256
#define HW_ 32768
#define C_  64
#define L_  4
#define NM_ 288      // 24 kx * 12 ky
#define KX_ 24
#define NT_ 14

// ---------------- device scratch (no runtime allocation allowed) ----------------
__device__ float dXa[(size_t)B_ * C_ * HW_];        // 268 MB
__device__ float dXb[(size_t)B_ * C_ * HW_];        // 268 MB
__device__ float dZ [(size_t)B_ * HW_ * 128];       // 537 MB
__device__ float dG [B_ * HW_];
__device__ float dG1[B_ * C_];
__device__ float dTmp[(size_t)B_ * C_ * HH * 24];   // row-DFT (12 complex interleaved)
__device__ float dF  [(size_t)B_ * NM_ * C_ * 2];   // spectrum [b][m][c] complex
__device__ float dF2 [(size_t)B_ * NM_ * C_ * 2];   // mixed spectrum
__device__ float dP  [(size_t)B_ * HH * C_ * 24];   // folded inverse coeffs [b][h][o][24]
__device__ float dWt [(size_t)L_ * NM_ * C_ * C_ * 2]; // spectral W [l][m][i][o] cplx
__device__ float dTwT[NT_ * C_ * 9 * C_];           // conv W transposed [t][ic][k][o]
__device__ float dTab1 [256 * 24];                  // fwd row-DFT [w][2ky]=cos,[2ky+1]=-sin
__device__ float dTab2c[KX_ * 128];                 // cos(2pi kx h/128)
__device__ float dTab2s[KX_ * 128];                 // sin(2pi kx h/128)
__device__ float dBas  [24 * 256];                  // inverse W basis rows

__device__ __forceinline__ float gelu(float x) {
    return 0.5f * x * (1.0f + erff(x * 0.70710678118654752f));
}

// ---------------- tables ----------------
__global__ void k_tab() {
    int i = blockIdx.x * blockDim.x + threadIdx.x;
    const double PI2 = 6.283185307179586476925286766559;
    if (i < 6144) {
        int w = i / 24, j = i % 24, ky = j >> 1;
        double ang = PI2 * (double)ky * (double)w / 256.0;
        dTab1[i] = (float)((j & 1) ? -sin(ang) : cos(ang));
    } else if (i < 9216) {
        int q = i - 6144;
        int kxi = q >> 7, h = q & 127;
        int kxv = (kxi < 12) ? kxi : (104 + kxi);   // 116..127
        double ang = PI2 * (double)kxv * (double)h / 128.0;
        dTab2c[q] = (float)cos(ang);
        dTab2s[q] = (float)sin(ang);
    } else if (i < 15360) {
        int q = i - 9216;
        int j = q >> 8, w = q & 255;
        float v;
        if (j == 0)       v = 1.0f;
        else if (j <= 11) v = (float)cos(PI2 * (double)j * (double)w / 256.0);
        else if (j <= 22) v = (float)sin(PI2 * (double)(j - 11) * (double)w / 256.0);
        else              v = 0.0f;
        dBas[q] = v;
    }
}

// ---------------- weight re-layouts ----------------
__global__ void k_wt(const float* __restrict__ w1r, const float* __restrict__ w1i,
                     const float* __restrict__ w2r, const float* __restrict__ w2i,
                     const float* __restrict__ tw) {
    const size_t N1 = (size_t)L_ * NM_ * C_ * C_;          // 4,718,592
    const size_t N2 = (size_t)NT_ * C_ * 9 * C_;           // 516,096
    size_t stride = (size_t)gridDim.x * blockDim.x;
    for (size_t idx = (size_t)blockIdx.x * blockDim.x + threadIdx.x;
         idx < N1 + N2; idx += stride) {
        if (idx < N1) {
            int o = (int)(idx & 63);
            int i = (int)((idx >> 6) & 63);
            int m = (int)((idx >> 12) % NM_);
            int l = (int)(idx / ((size_t)NM_ * C_ * C_));
            int kxi = m / 12, ky = m % 12;
            size_t s; float re, im;
            if (kxi < 12) {
                s = ((size_t)(l * C_ + i) * C_ + o) * 144 + kxi * 12 + ky;
                re = w1r[s]; im = w1i[s];
            } else {
                s = ((size_t)(l * C_ + i) * C_ + o) * 144 + (kxi - 12) * 12 + ky;
                re = w2r[s]; im = w2i[s];
            }
            dWt[idx * 2]     = re;
            dWt[idx * 2 + 1] = im;
        } else {
            size_t q = idx - N1;
            int o  = (int)(q & 63);
            int k  = (int)((q >> 6) % 9);
            int ic = (int)((q / (64 * 9)) & 63);
            int t  = (int)(q / ((size_t)C_ * 9 * C_));
            dTwT[q] = tw[((size_t)(t * C_ + o) * C_ + ic) * 9 + k];
        }
    }
}

// ---------------- ext embedding -> g1 (B x 64) ----------------
__global__ void k_g1(const float* __restrict__ ext, const float* __restrict__ day,
                     const float* __restrict__ hour, const float* __restrict__ e1w,
                     const float* __restrict__ e1b) {
    int b = blockIdx.x, o = threadIdx.x;
    float e0 = ext[b * 6 + 0];
    int d  = (int)ext[b * 6 + 2];
    int hh = (int)ext[b * 6 + 3];
    float emb[6] = { e0, day[d * 2], day[d * 2 + 1],
                     hour[hh * 3], hour[hh * 3 + 1], hour[hh * 3 + 2] };
    float acc = e1b[o];
#pragma unroll
    for (int k = 0; k < 6; k++) acc += emb[k] * e1w[o * 6 + k];
    dG1[b * 64 + o] = gelu(acc);
}

// ---------------- g per pixel (B x HW) ----------------
__global__ void k_g2(const float* __restrict__ e2w, const float* __restrict__ e2b) {
    __shared__ float g1s[B_ * C_];
    int tid = threadIdx.x;
    for (int i = tid; i < B_ * C_; i += 256) g1s[i] = dG1[i];
    __syncthreads();
    int p = blockIdx.x * 256 + tid;
    float4 wk[16];
    const float4* wp = (const float4*)(e2w + (size_t)p * 64);
#pragma unroll
    for (int i = 0; i < 16; i++) wk[i] = wp[i];
    float bias = e2b[p];
    for (int b = 0; b < B_; b++) {
        float acc = bias;
        const float* g1 = g1s + b * 64;
#pragma unroll
        for (int i = 0; i < 16; i++) {
            float4 w4 = wk[i];
            acc += w4.x * g1[4*i] + w4.y * g1[4*i+1] + w4.z * g1[4*i+2] + w4.w * g1[4*i+3];
        }
        dG[(size_t)b * HW_ + p] = gelu(acc);
    }
}

// ---------------- encoder: (inp,g) -> X[b][c][h][w] ----------------
__global__ void k_enc(const float* __restrict__ inp, const float* __restrict__ encw,
                      const float* __restrict__ encb) {
    __shared__ float ew[64 * 5];
    __shared__ float eb[64];
    int tid = threadIdx.x;
    if (tid < 320) ew[tid] = encw[tid];
    if (tid < 64)  eb[tid] = encb[tid];
    __syncthreads();
    int pg = blockIdx.x * 256 + tid;       // b*HW + p
    int b = pg >> 15, p = pg & 32767;
    float4 in4 = ((const float4*)inp)[pg];
    float g = dG[pg];
    float* out = dXa + (size_t)b * C_ * HW_ + p;
#pragma unroll 8
    for (int c = 0; c < 64; c++) {
        const float* w = ew + c * 5;
        out[(size_t)c * HW_] = eb[c] + in4.x*w[0] + in4.y*w[1] + in4.z*w[2] + in4.w*w[3] + g*w[4];
    }
}

// ---------------- FWD1: truncated row DFT (rows x 256)*(256 x 24) ----------------
__global__ void k_fwd1(const float* __restrict__ X) {
    __shared__ float As[256][33];
    __shared__ float Bs[32][24];
    int tid = threadIdx.x;
    int row0 = blockIdx.x * 256;
    int r2 = tid >> 1;            // 0..127 -> rows r2*2, r2*2+1
    int jg = tid & 1;             // output half: j = jg*12 + jj
    int ra = r2 * 2, rb = ra + 1;
    float acc0[12], acc1[12];
#pragma unroll
    for (int j = 0; j < 12; j++) { acc0[j] = 0.0f; acc1[j] = 0.0f; }
    for (int kt = 0; kt < 8; kt++) {
        int k0 = kt * 32;
        __syncthreads();
        for (int i = tid; i < 8192; i += 256) {
            int r = i >> 5, k = i & 31;
            As[r][k] = X[(size_t)(row0 + r) * 256 + k0 + k];
        }
        for (int i = tid; i < 768; i += 256) {
            int k = i / 24, j = i % 24;
            Bs[k][j] = dTab1[(k0 + k) * 24 + j];
        }
        __syncthreads();
#pragma unroll 8
        for (int k = 0; k < 32; k++) {
            float a0 = As[ra][k], a1 = As[rb][k];
#pragma unroll
            for (int jj = 0; jj < 12; jj++) {
                float bv = Bs[k][jg * 12 + jj];
                acc0[jj] += a0 * bv;
                acc1[jj] += a1 * bv;
            }
        }
    }
#pragma unroll
    for (int jj = 0; jj < 12; jj++) {
        dTmp[(size_t)(row0 + ra) * 24 + jg * 12 + jj] = acc0[jj];
        dTmp[(size_t)(row0 + rb) * 24 + jg * 12 + jj] = acc1[jj];
    }
}

// ---------------- FWD2: column DFT (128 h -> 24 kx), scatter to [b][m][c] ----------------
__global__ void k_fwd2() {
    __shared__ float ts[128 * 24];
    __shared__ float c2s[KX_ * 129];
    __shared__ float s2s[KX_ * 129];
    int tid = threadIdx.x;          // 288
    int bc = blockIdx.x;            // b*64 + c
    int b = bc >> 6, c = bc & 63;
    for (int i = tid; i < 3072; i += 288) ts[i] = dTmp[(size_t)bc * 3072 + i];
    for (int i = tid; i < 3072; i += 288) {
        int kxi = i >> 7, h = i & 127;
        c2s[kxi * 129 + h] = dTab2c[i];
        s2s[kxi * 129 + h] = dTab2s[i];
    }
    __syncthreads();
    int kxi = tid / 12, ky = tid % 12;
    float re = 0.0f, im = 0.0f;
#pragma unroll 4
    for (int h = 0; h < 128; h++) {
        float tr = ts[h * 24 + 2 * ky], ti = ts[h * 24 + 2 * ky + 1];
        float cv = c2s[kxi * 129 + h], sv = s2s[kxi * 129 + h];
        re += tr * cv + ti * sv;     // e^{-i theta}
        im += ti * cv - tr * sv;
    }
    ((float2*)dF)[((size_t)b * NM_ + tid) * 64 + c] = make_float2(re, im);
}

// ---------------- MIX: per-mode 64x64 complex channel mix ----------------
__global__ void k_mix(int l) {
    __shared__ float2 Ws[64 * 64];
    __shared__ float2 Fs[8 * 64];
    int m = blockIdx.x, bq = blockIdx.y;    // 288 x 4
    int tid = threadIdx.x;                  // 256
    const float2* wt = ((const float2*)dWt) + ((size_t)l * NM_ + m) * 4096;
    for (int i = tid; i < 4096; i += 256) Ws[i] = wt[i];
    const float2* fp = (const float2*)dF;
    for (int i = tid; i < 512; i += 256) {
        int bi = i >> 6, cc = i & 63;
        Fs[i] = fp[((size_t)(bq * 8 + bi) * NM_ + m) * 64 + cc];
    }
    __syncthreads();
    int o = tid & 63, bs = tid >> 6;        // bs 0..3, handles bi = bs, bs+4
    float2* out2 = (float2*)dF2;
#pragma unroll
    for (int half = 0; half < 2; half++) {
        int bi = bs + half * 4;
        float ar = 0.0f, ai = 0.0f;
#pragma unroll 8
        for (int cc = 0; cc < 64; cc++) {
            float2 f  = Fs[bi * 64 + cc];
            float2 wv = Ws[cc * 64 + o];
            ar += f.x * wv.x - f.y * wv.y;
            ai += f.x * wv.y + f.y * wv.x;
        }
        out2[((size_t)(bq * 8 + bi) * NM_ + m) * 64 + o] = make_float2(ar, ai);
    }
}

// ---------------- INV1: 24 kx -> 128 h, fold scale/weights into P ----------------
__global__ void k_inv1() {
    __shared__ float2 Gs[NM_];
    int bo = blockIdx.x;            // b*64 + o
    int b = bo >> 6, o = bo & 63;
    int h = threadIdx.x;            // 128
    const float2* fp = (const float2*)dF2;
    for (int i = h; i < NM_; i += 128)
        Gs[i] = fp[((size_t)b * NM_ + i) * 64 + o];
    __syncthreads();
    float cr[12], ci[12];
#pragma unroll
    for (int j = 0; j < 12; j++) { cr[j] = 0.0f; ci[j] = 0.0f; }
#pragma unroll 4
    for (int kxi = 0; kxi < 24; kxi++) {
        float cv = dTab2c[kxi * 128 + h];
        float sv = dTab2s[kxi * 128 + h];
#pragma unroll
        for (int ky = 0; ky < 12; ky++) {
            float2 g = Gs[kxi * 12 + ky];
            cr[ky] += g.x * cv - g.y * sv;   // e^{+i theta}
            ci[ky] += g.x * sv + g.y * cv;
        }
    }
    const float sc = 1.0f / 32768.0f;
    float* P = dP + ((size_t)(b * 128 + h) * 64 + o) * 24;
    P[0] = cr[0] * sc;
#pragma unroll
    for (int j = 1; j <= 11; j++)  P[j]      =  2.0f * sc * cr[j];
#pragma unroll
    for (int j = 1; j <= 11; j++)  P[11 + j] = -2.0f * sc * ci[j];
    P[23] = 0.0f;
}

// ---------------- COMBINE: inverse row DFT + channel mix + bias (+gelu) ----------------
__global__ void __launch_bounds__(256) k_combine(
        const float* __restrict__ src, float* __restrict__ dst,
        const float* __restrict__ wsw, const float* __restrict__ wsb, int act) {
    __shared__ float Ps[64 * 24];
    __shared__ float ws[64 * 64];
    __shared__ float wb[64];
    int bh = blockIdx.x;            // b*128 + h
    int b = bh >> 7, h = bh & 127;
    int w = threadIdx.x;            // 256
    const float* pbase = dP + (size_t)bh * 64 * 24;
    for (int i = w; i < 1536; i += 256) Ps[i] = pbase[i];
    for (int i = w; i < 4096; i += 256) ws[i] = wsw[i];
    if (w < 64) wb[w] = wsb[w];

    float bas[23];
#pragma unroll
    for (int j = 0; j < 23; j++) bas[j] = dBas[j * 256 + w];
    float xr[64];
    const float* sp = src + ((size_t)b * 64 * 128 + h) * 256 + w;
#pragma unroll
    for (int c = 0; c < 64; c++) xr[c] = sp[(size_t)c * HW_];
    __syncthreads();

    float* dp = dst + ((size_t)b * 64 * 128 + h) * 256 + w;
    for (int o = 0; o < 64; o++) {
        float acc = wb[o];
        const float* pr = Ps + o * 24;
#pragma unroll
        for (int j = 0; j < 23; j++) acc += pr[j] * bas[j];
        const float* wr = ws + o * 64;
#pragma unroll
        for (int c = 0; c < 64; c++) acc += wr[c] * xr[c];
        if (act) acc = gelu(acc);
        dp[(size_t)o * HW_] = acc;
    }
}

// ---------------- CONV: per-batch 3x3 SAME + gelu, output [px][o] ----------------
__global__ void __launch_bounds__(256) k_conv(
        const float* __restrict__ X, float* __restrict__ out,
        const float* __restrict__ ext, const float* __restrict__ tb) {
    __shared__ float inS[32 * 6 * 34];       // 32-channel chunk, 6 rows, 34 cols
    int blk = blockIdx.x;                    // 32 b x 32 ht x 8 wt
    int b  = blk >> 8;
    int ht = (blk >> 3) & 31;
    int wt = blk & 7;
    int h0 = ht * 4, w0 = wt * 32;
    int tid = threadIdx.x;
    int o = tid & 63, rsel = tid >> 6;       // warp = 32 consecutive o, same rsel
    int t = (int)ext[b * 6 + 3] - 5;
    float tbv = tb[t * 64 + o];

    float acc[32];
#pragma unroll
    for (int i = 0; i < 32; i++) acc[i] = 0.0f;

    for (int icb = 0; icb < 64; icb += 32) {
        __syncthreads();
        for (int i = tid; i < 32 * 204; i += 256) {
            int ic = i / 204, rem = i % 204;
            int r = rem / 34, cc = rem % 34;
            int gh = h0 - 1 + r, gw = w0 - 1 + cc;
            float v = 0.0f;
            if (gh >= 0 && gh < 128 && gw >= 0 && gw < 256)
                v = X[((size_t)(b * 64 + icb + ic) * 128 + gh) * 256 + gw];
            inS[i] = v;
        }
        __syncthreads();
        for (int ic = 0; ic < 32; ic++) {
            const float* wp = dTwT + ((size_t)(t * 64 + icb + ic) * 9) * 64 + o;
            float wv[9];
#pragma unroll
            for (int k = 0; k < 9; k++) wv[k] = wp[k * 64];
            const float* S = inS + ic * 204 + rsel * 34;
            float a0 = S[0],      a1 = S[34],      a2 = S[68];
            float b0 = S[1],      b1 = S[35],      b2 = S[69];
#pragma unroll
            for (int wi = 0; wi < 32; wi++) {
                float c0 = S[wi + 2], c1 = S[34 + wi + 2], c2 = S[68 + wi + 2];
                acc[wi] += a0 * wv[0] + b0 * wv[1] + c0 * wv[2]
                         + a1 * wv[3] + b1 * wv[4] + c1 * wv[5]
                         + a2 * wv[6] + b2 * wv[7] + c2 * wv[8];
                a0 = b0; a1 = b1; a2 = b2;
                b0 = c0; b1 = c1; b2 = c2;
            }
        }
    }
    int h = h0 + rsel;
    size_t pxb = (size_t)b * HW_ + (size_t)h * 256 + w0;
#pragma unroll
    for (int wi = 0; wi < 32; wi++)
        out[(pxb + wi) * 64 + o] = gelu(acc[wi] + tbv);
}

// ---------------- MLP1: [1M x 64] x [64 x 128] + gelu ----------------
__global__ void __launch_bounds__(256) k_mlp1(
        const float* __restrict__ hf, const float* __restrict__ f1w,
        const float* __restrict__ f1b) {
    __shared__ float As[128 * 33];
    __shared__ float Ws[128 * 33];
    __shared__ float bS[128];
    int tid = threadIdx.x;
    int px0 = blockIdx.x * 128;
    int pxg = tid >> 4, jg = tid & 15;
    float acc[8][8];
#pragma unroll
    for (int i = 0; i < 8; i++)
#pragma unroll
        for (int j = 0; j < 8; j++) acc[i][j] = 0.0f;
    if (tid < 128) bS[tid] = f1b[tid];

    for (int kc = 0; kc < 64; kc += 32) {
        __syncthreads();
        for (int i = tid; i < 4096; i += 256) {
            int r = i >> 5, c = i & 31;
            As[r * 33 + c] = hf[(size_t)(px0 + r) * 64 + kc + c];
            Ws[r * 33 + c] = f1w[(size_t)r * 64 + kc + c];
        }
        __syncthreads();
#pragma unroll 8
        for (int c = 0; c < 32; c++) {
            float af[8], bf[8];
#pragma unroll
            for (int i = 0; i < 8; i++) af[i] = As[(pxg * 8 + i) * 33 + c];
#pragma unroll
            for (int j = 0; j < 8; j++) bf[j] = Ws[(jg * 8 + j) * 33 + c];
#pragma unroll
            for (int i = 0; i < 8; i++)
#pragma unroll
                for (int j = 0; j < 8; j++) acc[i][j] += af[i] * bf[j];
        }
    }
#pragma unroll
    for (int i = 0; i < 8; i++) {
        int px = px0 + pxg * 8 + i;
        float* zp = dZ + (size_t)px * 128 + jg * 8;
        float4 v0, v1;
        v0.x = gelu(acc[i][0] + bS[jg*8+0]); v0.y = gelu(acc[i][1] + bS[jg*8+1]);
        v0.z = gelu(acc[i][2] + bS[jg*8+2]); v0.w = gelu(acc[i][3] + bS[jg*8+3]);
        v1.x = gelu(acc[i][4] + bS[jg*8+4]); v1.y = gelu(acc[i][5] + bS[jg*8+5]);
        v1.z = gelu(acc[i][6] + bS[jg*8+6]); v1.w = gelu(acc[i][7] + bS[jg*8+7]);
        ((float4*)zp)[0] = v0; ((float4*)zp)[1] = v1;
    }
}

// ---------------- MLP2: [1M x 128] x [128 x 64] + gelu -> dXa [px][64] ----------------
__global__ void __launch_bounds__(256) k_mlp2(
        const float* __restrict__ f2w, const float* __restrict__ f2b) {
    __shared__ float As[128 * 33];
    __shared__ float Ws[64 * 33];
    __shared__ float bS[64];
    int tid = threadIdx.x;
    int px0 = blockIdx.x * 128;
    int pxg = tid >> 3, og = tid & 7;       // 32 px-groups x4, 8 o-groups x8
    float acc[4][8];
#pragma unroll
    for (int i = 0; i < 4; i++)
#pragma unroll
        for (int j = 0; j < 8; j++) acc[i][j] = 0.0f;
    if (tid < 64) bS[tid] = f2b[tid];

    for (int kc = 0; kc < 128; kc += 32) {
        __syncthreads();
        for (int i = tid; i < 4096; i += 256) {
            int r = i >> 5, c = i & 31;
            As[r * 33 + c] = dZ[(size_t)(px0 + r) * 128 + kc + c];
        }
        for (int i = tid; i < 2048; i += 256) {
            int r = i >> 5, c = i & 31;
            Ws[r * 33 + c] = f2w[(size_t)r * 128 + kc + c];
        }
        __syncthreads();
#pragma unroll 8
        for (int c = 0; c < 32; c++) {
            float af[4], bf[8];
#pragma unroll
            for (int i = 0; i < 4; i++) af[i] = As[(pxg * 4 + i) * 33 + c];
#pragma unroll
            for (int j = 0; j < 8; j++) bf[j] = Ws[(og * 8 + j) * 33 + c];
#pragma unroll
            for (int i = 0; i < 4; i++)
#pragma unroll
                for (int j = 0; j < 8; j++) acc[i][j] += af[i] * bf[j];
        }
    }
#pragma unroll
    for (int i = 0; i < 4; i++) {
        int px = px0 + pxg * 4 + i;
        float* zp = dXa + (size_t)px * 64 + og * 8;
        float4 v0, v1;
        v0.x = gelu(acc[i][0] + bS[og*8+0]); v0.y = gelu(acc[i][1] + bS[og*8+1]);
        v0.z = gelu(acc[i][2] + bS[og*8+2]); v0.w = gelu(acc[i][3] + bS[og*8+3]);
        v1.x = gelu(acc[i][4] + bS[og*8+4]); v1.y = gelu(acc[i][5] + bS[og*8+5]);
        v1.z = gelu(acc[i][6] + bS[og*8+6]); v1.w = gelu(acc[i][7] + bS[og*8+7]);
        ((float4*)zp)[0] = v0; ((float4*)zp)[1] = v1;
    }
}

// ---------------- MLP3: z2 (dXa [px][64]) -> out [px][2] ----------------
__global__ void k_mlp3(const float* __restrict__ f3w, const float* __restrict__ f3b,
                       float* __restrict__ out) {
    __shared__ float w3[128];
    __shared__ float b3[2];
    int tid = threadIdx.x;
    if (tid < 128) w3[tid] = f3w[tid];
    if (tid < 2)   b3[tid] = f3b[tid];
    __syncthreads();
    int px = blockIdx.x * 256 + tid;
    const float4* zp = (const float4*)(dXa + (size_t)px * 64);
    float a0 = b3[0], a1 = b3[1];
#pragma unroll
    for (int i = 0; i < 16; i++) {
        float4 z = zp[i];
        a0 += z.x * w3[4*i] + z.y * w3[4*i+1] + z.z * w3[4*i+2] + z.w * w3[4*i+3];
        a1 += z.x * w3[64+4*i] + z.y * w3[64+4*i+1] + z.z * w3[64+4*i+2] + z.w * w3[64+4*i+3];
    }
    ((float2*)out)[px] = make_float2(a0, a1);
}

// ---------------- launch ----------------
extern "C" void kernel_launch(void* const* d_in, const int* in_sizes, int n_in,
                              void* d_out, int out_size) {
    const float* inp   = (const float*)d_in[0];
    const float* ext   = (const float*)d_in[1];
    const float* enc_w = (const float*)d_in[2];
    const float* enc_b = (const float*)d_in[3];
    const float* w1r   = (const float*)d_in[4];
    const float* w1i   = (const float*)d_in[5];
    const float* w2r   = (const float*)d_in[6];
    const float* w2i   = (const float*)d_in[7];
    const float* ws_w  = (const float*)d_in[8];
    const float* ws_b  = (const float*)d_in[9];
    const float* day   = (const float*)d_in[10];
    const float* hour  = (const float*)d_in[11];
    const float* e1w   = (const float*)d_in[12];
    const float* e1b   = (const float*)d_in[13];
    const float* e2w   = (const float*)d_in[14];
    const float* e2b   = (const float*)d_in[15];
    const float* tw    = (const float*)d_in[16];
    const float* tb    = (const float*)d_in[17];
    const float* f1w   = (const float*)d_in[18];
    const float* f1b   = (const float*)d_in[19];
    const float* f2w   = (const float*)d_in[20];
    const float* f2b   = (const float*)d_in[21];
    const float* f3w   = (const float*)d_in[22];
    const float* f3b   = (const float*)d_in[23];
    float* out = (float*)d_out;

    k_tab<<<60, 256>>>();
    k_wt<<<2048, 256>>>(w1r, w1i, w2r, w2i, tw);
    k_g1<<<32, 64>>>(ext, day, hour, e1w, e1b);
    k_g2<<<128, 256>>>(e2w, e2b);
    k_enc<<<4096, 256>>>(inp, enc_w, enc_b);

    float* bufA; float* bufB;
    cudaGetSymbolAddress((void**)&bufA, dXa);
    cudaGetSymbolAddress((void**)&bufB, dXb);

    float* src = bufA;
    float* dst = bufB;
    for (int l = 0; l < L_; l++) {
        k_fwd1<<<1024, 256>>>(src);
        k_fwd2<<<2048, 288>>>();
        k_mix<<<dim3(288, 4), 256>>>(l);
        k_inv1<<<2048, 128>>>();
        k_combine<<<4096, 256>>>(src, dst, ws_w + (size_t)l * 4096,
                                 ws_b + (size_t)l * 64, (l != L_ - 1) ? 1 : 0);
        float* t2 = src; src = dst; dst = t2;
    }
    // final x is in src (== bufA after 4 swaps)
    k_conv<<<8192, 256>>>(src, dst, ext, tb);   // hfeat -> dst = bufB [px][64]
    k_mlp1<<<8192, 256>>>(dst, f1w, f1b);       // -> dZ
    k_mlp2<<<8192, 256>>>(f2w, f2b);            // -> dXa [px][64]
    k_mlp3<<<4096, 256>>>(f3w, f3b, out);
}

// round 5
// speedup vs baseline: 1.1822x; 1.1822x over previous
#include <cuda_runtime.h>
#include <math.h>

#define B_  32
#define HH  128
#define WW  256
#define HW_ 32768
#define C_  64
#define L_  4
#define NM_ 288      // 24 kx * 12 ky
#define KX_ 24
#define NT_ 14

typedef unsigned long long ull;

// ---------------- device scratch (no runtime allocation allowed) ----------------
__device__ float dXa[(size_t)B_ * C_ * HW_];
__device__ float dXb[(size_t)B_ * C_ * HW_];
__device__ float dZ [(size_t)B_ * HW_ * 128];
__device__ float dG [B_ * HW_];
__device__ float dG1[B_ * C_];
__device__ float dTmp[(size_t)B_ * C_ * HH * 24];
__device__ float dF  [(size_t)B_ * NM_ * C_ * 2];
__device__ float dF2 [(size_t)B_ * NM_ * C_ * 2];
__device__ __align__(16) float dP  [(size_t)B_ * HH * C_ * 24];
__device__ float dWt [(size_t)L_ * NM_ * C_ * C_ * 2];
__device__ __align__(16) float dTwT[NT_ * C_ * 9 * C_];   // [t][ic][k][o]
__device__ float dTab1 [256 * 24];
__device__ float dTab2c[KX_ * 128];
__device__ float dTab2s[KX_ * 128];
__device__ float dBas  [24 * 256];

__device__ __forceinline__ float gelu(float x) {
    return 0.5f * x * (1.0f + erff(x * 0.70710678118654752f));
}

// -------- packed f32x2 helpers --------
__device__ __forceinline__ ull pk2(float lo, float hi) {
    ull r; asm("mov.b64 %0,{%1,%2};" : "=l"(r) : "f"(lo), "f"(hi)); return r;
}
__device__ __forceinline__ ull pkb(float v) { return pk2(v, v); }
__device__ __forceinline__ ull f2fma(ull a, ull b, ull c) {
    ull d; asm("fma.rn.f32x2 %0,%1,%2,%3;" : "=l"(d) : "l"(a), "l"(b), "l"(c)); return d;
}
__device__ __forceinline__ float2 upk(ull v) {
    float2 r; asm("mov.b64 {%0,%1},%2;" : "=f"(r.x), "=f"(r.y) : "l"(v)); return r;
}

// ---------------- tables ----------------
__global__ void k_tab() {
    int i = blockIdx.x * blockDim.x + threadIdx.x;
    const double PI2 = 6.283185307179586476925286766559;
    if (i < 6144) {
        int w = i / 24, j = i % 24, ky = j >> 1;
        double ang = PI2 * (double)ky * (double)w / 256.0;
        dTab1[i] = (float)((j & 1) ? -sin(ang) : cos(ang));
    } else if (i < 9216) {
        int q = i - 6144;
        int kxi = q >> 7, h = q & 127;
        int kxv = (kxi < 12) ? kxi : (104 + kxi);
        double ang = PI2 * (double)kxv * (double)h / 128.0;
        dTab2c[q] = (float)cos(ang);
        dTab2s[q] = (float)sin(ang);
    } else if (i < 15360) {
        int q = i - 9216;
        int j = q >> 8, w = q & 255;
        float v;
        if (j == 0)       v = 1.0f;
        else if (j <= 11) v = (float)cos(PI2 * (double)j * (double)w / 256.0);
        else if (j <= 22) v = (float)sin(PI2 * (double)(j - 11) * (double)w / 256.0);
        else              v = 0.0f;
        dBas[q] = v;
    }
}

// ---------------- weight re-layouts ----------------
__global__ void k_wt(const float* __restrict__ w1r, const float* __restrict__ w1i,
                     const float* __restrict__ w2r, const float* __restrict__ w2i,
                     const float* __restrict__ tw) {
    const size_t N1 = (size_t)L_ * NM_ * C_ * C_;
    const size_t N2 = (size_t)NT_ * C_ * 9 * C_;
    size_t stride = (size_t)gridDim.x * blockDim.x;
    for (size_t idx = (size_t)blockIdx.x * blockDim.x + threadIdx.x;
         idx < N1 + N2; idx += stride) {
        if (idx < N1) {
            int o = (int)(idx & 63);
            int i = (int)((idx >> 6) & 63);
            int m = (int)((idx >> 12) % NM_);
            int l = (int)(idx / ((size_t)NM_ * C_ * C_));
            int kxi = m / 12, ky = m % 12;
            size_t s; float re, im;
            if (kxi < 12) {
                s = ((size_t)(l * C_ + i) * C_ + o) * 144 + kxi * 12 + ky;
                re = w1r[s]; im = w1i[s];
            } else {
                s = ((size_t)(l * C_ + i) * C_ + o) * 144 + (kxi - 12) * 12 + ky;
                re = w2r[s]; im = w2i[s];
            }
            dWt[idx * 2]     = re;
            dWt[idx * 2 + 1] = im;
        } else {
            size_t q = idx - N1;
            int o  = (int)(q & 63);
            int k  = (int)((q >> 6) % 9);
            int ic = (int)((q / (64 * 9)) & 63);
            int t  = (int)(q / ((size_t)C_ * 9 * C_));
            dTwT[q] = tw[((size_t)(t * C_ + o) * C_ + ic) * 9 + k];
        }
    }
}

// ---------------- ext embedding -> g1 ----------------
__global__ void k_g1(const float* __restrict__ ext, const float* __restrict__ day,
                     const float* __restrict__ hour, const float* __restrict__ e1w,
                     const float* __restrict__ e1b) {
    int b = blockIdx.x, o = threadIdx.x;
    float e0 = ext[b * 6 + 0];
    int d  = (int)ext[b * 6 + 2];
    int hh = (int)ext[b * 6 + 3];
    float emb[6] = { e0, day[d * 2], day[d * 2 + 1],
                     hour[hh * 3], hour[hh * 3 + 1], hour[hh * 3 + 2] };
    float acc = e1b[o];
#pragma unroll
    for (int k = 0; k < 6; k++) acc += emb[k] * e1w[o * 6 + k];
    dG1[b * 64 + o] = gelu(acc);
}

// ---------------- g per pixel ----------------
__global__ void k_g2(const float* __restrict__ e2w, const float* __restrict__ e2b) {
    __shared__ float g1s[B_ * C_];
    int tid = threadIdx.x;
    for (int i = tid; i < B_ * C_; i += 256) g1s[i] = dG1[i];
    __syncthreads();
    int p = blockIdx.x * 256 + tid;
    float4 wk[16];
    const float4* wp = (const float4*)(e2w + (size_t)p * 64);
#pragma unroll
    for (int i = 0; i < 16; i++) wk[i] = wp[i];
    float bias = e2b[p];
    for (int b = 0; b < B_; b++) {
        float acc = bias;
        const float* g1 = g1s + b * 64;
#pragma unroll
        for (int i = 0; i < 16; i++) {
            float4 w4 = wk[i];
            acc += w4.x * g1[4*i] + w4.y * g1[4*i+1] + w4.z * g1[4*i+2] + w4.w * g1[4*i+3];
        }
        dG[(size_t)b * HW_ + p] = gelu(acc);
    }
}

// ---------------- encoder ----------------
__global__ void k_enc(const float* __restrict__ inp, const float* __restrict__ encw,
                      const float* __restrict__ encb) {
    __shared__ float ew[64 * 5];
    __shared__ float eb[64];
    int tid = threadIdx.x;
    if (tid < 320) ew[tid] = encw[tid];
    if (tid < 64)  eb[tid] = encb[tid];
    __syncthreads();
    int pg = blockIdx.x * 256 + tid;
    int b = pg >> 15, p = pg & 32767;
    float4 in4 = ((const float4*)inp)[pg];
    float g = dG[pg];
    float* out = dXa + (size_t)b * C_ * HW_ + p;
#pragma unroll 8
    for (int c = 0; c < 64; c++) {
        const float* w = ew + c * 5;
        out[(size_t)c * HW_] = eb[c] + in4.x*w[0] + in4.y*w[1] + in4.z*w[2] + in4.w*w[3] + g*w[4];
    }
}

// ---------------- FWD1: truncated row DFT ----------------
__global__ void k_fwd1(const float* __restrict__ X) {
    __shared__ float As[256][33];
    __shared__ float Bs[32][24];
    int tid = threadIdx.x;
    int row0 = blockIdx.x * 256;
    int r2 = tid >> 1;
    int jg = tid & 1;
    int ra = r2 * 2, rb = ra + 1;
    float acc0[12], acc1[12];
#pragma unroll
    for (int j = 0; j < 12; j++) { acc0[j] = 0.0f; acc1[j] = 0.0f; }
    for (int kt = 0; kt < 8; kt++) {
        int k0 = kt * 32;
        __syncthreads();
        for (int i = tid; i < 8192; i += 256) {
            int r = i >> 5, k = i & 31;
            As[r][k] = X[(size_t)(row0 + r) * 256 + k0 + k];
        }
        for (int i = tid; i < 768; i += 256) {
            int k = i / 24, j = i % 24;
            Bs[k][j] = dTab1[(k0 + k) * 24 + j];
        }
        __syncthreads();
#pragma unroll 8
        for (int k = 0; k < 32; k++) {
            float a0 = As[ra][k], a1 = As[rb][k];
#pragma unroll
            for (int jj = 0; jj < 12; jj++) {
                float bv = Bs[k][jg * 12 + jj];
                acc0[jj] += a0 * bv;
                acc1[jj] += a1 * bv;
            }
        }
    }
#pragma unroll
    for (int jj = 0; jj < 12; jj++) {
        dTmp[(size_t)(row0 + ra) * 24 + jg * 12 + jj] = acc0[jj];
        dTmp[(size_t)(row0 + rb) * 24 + jg * 12 + jj] = acc1[jj];
    }
}

// ---------------- FWD2 ----------------
__global__ void k_fwd2() {
    __shared__ float ts[128 * 24];
    __shared__ float c2s[KX_ * 129];
    __shared__ float s2s[KX_ * 129];
    int tid = threadIdx.x;          // 288
    int bc = blockIdx.x;
    int b = bc >> 6, c = bc & 63;
    for (int i = tid; i < 3072; i += 288) ts[i] = dTmp[(size_t)bc * 3072 + i];
    for (int i = tid; i < 3072; i += 288) {
        int kxi = i >> 7, h = i & 127;
        c2s[kxi * 129 + h] = dTab2c[i];
        s2s[kxi * 129 + h] = dTab2s[i];
    }
    __syncthreads();
    int kxi = tid / 12, ky = tid % 12;
    float re = 0.0f, im = 0.0f;
#pragma unroll 4
    for (int h = 0; h < 128; h++) {
        float tr = ts[h * 24 + 2 * ky], ti = ts[h * 24 + 2 * ky + 1];
        float cv = c2s[kxi * 129 + h], sv = s2s[kxi * 129 + h];
        re += tr * cv + ti * sv;
        im += ti * cv - tr * sv;
    }
    ((float2*)dF)[((size_t)b * NM_ + tid) * 64 + c] = make_float2(re, im);
}

// ---------------- MIX ----------------
__global__ void k_mix(int l) {
    __shared__ float2 Ws[64 * 64];
    __shared__ float2 Fs[8 * 64];
    int m = blockIdx.x, bq = blockIdx.y;
    int tid = threadIdx.x;
    const float2* wt = ((const float2*)dWt) + ((size_t)l * NM_ + m) * 4096;
    for (int i = tid; i < 4096; i += 256) Ws[i] = wt[i];
    const float2* fp = (const float2*)dF;
    for (int i = tid; i < 512; i += 256) {
        int bi = i >> 6, cc = i & 63;
        Fs[i] = fp[((size_t)(bq * 8 + bi) * NM_ + m) * 64 + cc];
    }
    __syncthreads();
    int o = tid & 63, bs = tid >> 6;
    float2* out2 = (float2*)dF2;
#pragma unroll
    for (int half = 0; half < 2; half++) {
        int bi = bs + half * 4;
        float ar = 0.0f, ai = 0.0f;
#pragma unroll 8
        for (int cc = 0; cc < 64; cc++) {
            float2 f  = Fs[bi * 64 + cc];
            float2 wv = Ws[cc * 64 + o];
            ar += f.x * wv.x - f.y * wv.y;
            ai += f.x * wv.y + f.y * wv.x;
        }
        out2[((size_t)(bq * 8 + bi) * NM_ + m) * 64 + o] = make_float2(ar, ai);
    }
}

// ---------------- INV1 ----------------
__global__ void k_inv1() {
    __shared__ float2 Gs[NM_];
    int bo = blockIdx.x;
    int b = bo >> 6, o = bo & 63;
    int h = threadIdx.x;
    const float2* fp = (const float2*)dF2;
    for (int i = h; i < NM_; i += 128)
        Gs[i] = fp[((size_t)b * NM_ + i) * 64 + o];
    __syncthreads();
    float cr[12], ci[12];
#pragma unroll
    for (int j = 0; j < 12; j++) { cr[j] = 0.0f; ci[j] = 0.0f; }
#pragma unroll 4
    for (int kxi = 0; kxi < 24; kxi++) {
        float cv = dTab2c[kxi * 128 + h];
        float sv = dTab2s[kxi * 128 + h];
#pragma unroll
        for (int ky = 0; ky < 12; ky++) {
            float2 g = Gs[kxi * 12 + ky];
            cr[ky] += g.x * cv - g.y * sv;
            ci[ky] += g.x * sv + g.y * cv;
        }
    }
    const float sc = 1.0f / 32768.0f;
    float* P = dP + ((size_t)(b * 128 + h) * 64 + o) * 24;
    P[0] = cr[0] * sc;
#pragma unroll
    for (int j = 1; j <= 11; j++)  P[j]      =  2.0f * sc * cr[j];
#pragma unroll
    for (int j = 1; j <= 11; j++)  P[11 + j] = -2.0f * sc * ci[j];
    P[23] = 0.0f;
}

// ---------------- COMBINE: inv row DFT + channel mix + bias (+gelu), f32x2 ----------------
__global__ void __launch_bounds__(256) k_combine(
        const float* __restrict__ src, float* __restrict__ dst,
        const float* __restrict__ wsw, const float* __restrict__ wsb, int act) {
    __shared__ __align__(16) float Ps[64 * 24];
    __shared__ __align__(16) float ws[64 * 64];
    __shared__ float wb[64];
    int bh = blockIdx.x;
    int b = bh >> 7, h = bh & 127;
    int w = threadIdx.x;
    const float* pbase = dP + (size_t)bh * 64 * 24;
    for (int i = w; i < 1536; i += 256) Ps[i] = pbase[i];
    for (int i = w; i < 4096; i += 256) ws[i] = wsw[i];
    if (w < 64) wb[w] = wsb[w];

    // basis pairs (bas[23] padded with 0; P[23]==0 so hi lane of pair 11 is inert)
    ull bp[12];
#pragma unroll
    for (int j = 0; j < 11; j++) bp[j] = pk2(dBas[(2*j) * 256 + w], dBas[(2*j+1) * 256 + w]);
    bp[11] = pk2(dBas[22 * 256 + w], 0.0f);

    // x pairs
    ull xp[32];
    const float* sp = src + ((size_t)b * 64 * 128 + h) * 256 + w;
#pragma unroll
    for (int i = 0; i < 32; i++)
        xp[i] = pk2(sp[(size_t)(2*i) * HW_], sp[(size_t)(2*i+1) * HW_]);
    __syncthreads();

    float* dp = dst + ((size_t)b * 64 * 128 + h) * 256 + w;
    for (int o = 0; o < 64; o++) {
        const float2* pr2 = (const float2*)(Ps + o * 24);
        const float2* wr2 = (const float2*)(ws + o * 64);
        ull acc2 = 0ull;
#pragma unroll
        for (int j = 0; j < 12; j++) {
            float2 p = pr2[j];
            acc2 = f2fma(bp[j], pk2(p.x, p.y), acc2);
        }
#pragma unroll
        for (int i = 0; i < 32; i++) {
            float2 wv = wr2[i];
            acc2 = f2fma(xp[i], pk2(wv.x, wv.y), acc2);
        }
        float2 r = upk(acc2);
        float acc = r.x + r.y + wb[o];
        if (act) acc = gelu(acc);
        dp[(size_t)o * HW_] = acc;
    }
}

// ---------------- CONV: 3x3 SAME + gelu, o-pair packed f32x2 ----------------
__global__ void __launch_bounds__(256) k_conv(
        const float* __restrict__ X, float* __restrict__ out,
        const float* __restrict__ ext, const float* __restrict__ tb) {
    __shared__ float inS[32 * 340];          // 32 ic chunk, 10 rows x 34 cols
    int blk = blockIdx.x;                    // 32 b x 16 ht x 8 wt
    int b  = blk >> 7;
    int ht = (blk >> 3) & 15;
    int wt = blk & 7;
    int h0 = ht * 8, w0 = wt * 32;
    int tid = threadIdx.x;
    int op = tid & 31, rsel = tid >> 5;      // o-pair (o=2*op), row 0..7
    int o = op * 2;
    int t = (int)ext[b * 6 + 3] - 5;
    float tb0 = tb[t * 64 + o], tb1 = tb[t * 64 + o + 1];

    ull acc[32];
#pragma unroll
    for (int i = 0; i < 32; i++) acc[i] = 0ull;

    for (int icb = 0; icb < 64; icb += 32) {
        __syncthreads();
        for (int i = tid; i < 32 * 340; i += 256) {
            int ic = i / 340, rem = i % 340;
            int r = rem / 34, cc = rem % 34;
            int gh = h0 - 1 + r, gw = w0 - 1 + cc;
            float v = 0.0f;
            if (gh >= 0 && gh < 128 && gw >= 0 && gw < 256)
                v = X[((size_t)(b * 64 + icb + ic) * 128 + gh) * 256 + gw];
            inS[i] = v;
        }
        __syncthreads();
        for (int ic = 0; ic < 32; ic++) {
            const float2* wp2 = (const float2*)(dTwT +
                ((size_t)(t * 64 + icb + ic) * 9) * 64 + o);
            ull wv[9];
#pragma unroll
            for (int k = 0; k < 9; k++) {
                float2 wf = wp2[k * 32];
                wv[k] = pk2(wf.x, wf.y);
            }
            const float* S = inS + ic * 340 + rsel * 34;
            ull a0 = pkb(S[0]),  a1 = pkb(S[34]), a2 = pkb(S[68]);
            ull b0 = pkb(S[1]),  b1 = pkb(S[35]), b2 = pkb(S[69]);
#pragma unroll
            for (int wi = 0; wi < 32; wi++) {
                ull c0 = pkb(S[wi + 2]), c1 = pkb(S[wi + 36]), c2 = pkb(S[wi + 70]);
                ull t0 = acc[wi];
                t0 = f2fma(a0, wv[0], t0);
                t0 = f2fma(b0, wv[1], t0);
                t0 = f2fma(c0, wv[2], t0);
                t0 = f2fma(a1, wv[3], t0);
                t0 = f2fma(b1, wv[4], t0);
                t0 = f2fma(c1, wv[5], t0);
                t0 = f2fma(a2, wv[6], t0);
                t0 = f2fma(b2, wv[7], t0);
                t0 = f2fma(c2, wv[8], t0);
                acc[wi] = t0;
                a0 = b0; a1 = b1; a2 = b2;
                b0 = c0; b1 = c1; b2 = c2;
            }
        }
    }
    int h = h0 + rsel;
    size_t pxb = (size_t)b * HW_ + (size_t)h * 256 + w0;
#pragma unroll
    for (int wi = 0; wi < 32; wi++) {
        float2 r = upk(acc[wi]);
        float2 ov;
        ov.x = gelu(r.x + tb0);
        ov.y = gelu(r.y + tb1);
        *(float2*)(out + (pxb + wi) * 64 + o) = ov;
    }
}

// ---------------- MLP1: [1M x 64] x [64 x 128] + gelu, f32x2 ----------------
__global__ void __launch_bounds__(256) k_mlp1(
        const float* __restrict__ hf, const float* __restrict__ f1w,
        const float* __restrict__ f1b) {
    __shared__ __align__(16) float As[128 * 34];
    __shared__ __align__(16) float Wt[32 * 130];   // [c][j]
    __shared__ float bS[128];
    int tid = threadIdx.x;
    int px0 = blockIdx.x * 128;
    int pxg = tid >> 4, jg = tid & 15;
    ull acc2[8][4];
#pragma unroll
    for (int i = 0; i < 8; i++)
#pragma unroll
        for (int j = 0; j < 4; j++) acc2[i][j] = 0ull;
    if (tid < 128) bS[tid] = f1b[tid];

    for (int kc = 0; kc < 64; kc += 32) {
        __syncthreads();
        for (int i = tid; i < 4096; i += 256) {
            int r = i >> 5, c = i & 31;
            As[r * 34 + c] = hf[(size_t)(px0 + r) * 64 + kc + c];
            Wt[c * 130 + r] = f1w[(size_t)r * 64 + kc + c];   // r = j here
        }
        __syncthreads();
#pragma unroll 8
        for (int c = 0; c < 32; c++) {
            ull afp[8];
#pragma unroll
            for (int i = 0; i < 8; i++) afp[i] = pkb(As[(pxg * 8 + i) * 34 + c]);
            const float2* bf2 = (const float2*)(Wt + c * 130 + jg * 8);
            ull b4[4];
#pragma unroll
            for (int j = 0; j < 4; j++) { float2 v = bf2[j]; b4[j] = pk2(v.x, v.y); }
#pragma unroll
            for (int i = 0; i < 8; i++)
#pragma unroll
                for (int j = 0; j < 4; j++) acc2[i][j] = f2fma(afp[i], b4[j], acc2[i][j]);
        }
    }
#pragma unroll
    for (int i = 0; i < 8; i++) {
        int px = px0 + pxg * 8 + i;
        float* zp = dZ + (size_t)px * 128 + jg * 8;
        float2 r0 = upk(acc2[i][0]), r1 = upk(acc2[i][1]);
        float2 r2 = upk(acc2[i][2]), r3 = upk(acc2[i][3]);
        float4 v0, v1;
        v0.x = gelu(r0.x + bS[jg*8+0]); v0.y = gelu(r0.y + bS[jg*8+1]);
        v0.z = gelu(r1.x + bS[jg*8+2]); v0.w = gelu(r1.y + bS[jg*8+3]);
        v1.x = gelu(r2.x + bS[jg*8+4]); v1.y = gelu(r2.y + bS[jg*8+5]);
        v1.z = gelu(r3.x + bS[jg*8+6]); v1.w = gelu(r3.y + bS[jg*8+7]);
        ((float4*)zp)[0] = v0; ((float4*)zp)[1] = v1;
    }
}

// ---------------- MLP2: [1M x 128] x [128 x 64] + gelu -> dXa, f32x2 ----------------
__global__ void __launch_bounds__(256) k_mlp2(
        const float* __restrict__ f2w, const float* __restrict__ f2b) {
    __shared__ __align__(16) float As[128 * 34];
    __shared__ __align__(16) float Wt[32 * 66];    // [c][o]
    __shared__ float bS[64];
    int tid = threadIdx.x;
    int px0 = blockIdx.x * 128;
    int pxg = tid >> 3, og = tid & 7;
    ull acc2[4][4];
#pragma unroll
    for (int i = 0; i < 4; i++)
#pragma unroll
        for (int j = 0; j < 4; j++) acc2[i][j] = 0ull;
    if (tid < 64) bS[tid] = f2b[tid];

    for (int kc = 0; kc < 128; kc += 32) {
        __syncthreads();
        for (int i = tid; i < 4096; i += 256) {
            int r = i >> 5, c = i & 31;
            As[r * 34 + c] = dZ[(size_t)(px0 + r) * 128 + kc + c];
        }
        for (int i = tid; i < 2048; i += 256) {
            int oo = i >> 5, c = i & 31;
            Wt[c * 66 + oo] = f2w[(size_t)oo * 128 + kc + c];
        }
        __syncthreads();
#pragma unroll 8
        for (int c = 0; c < 32; c++) {
            ull afp[4];
#pragma unroll
            for (int i = 0; i < 4; i++) afp[i] = pkb(As[(pxg * 4 + i) * 34 + c]);
            const float2* bf2 = (const float2*)(Wt + c * 66 + og * 8);
            ull b4[4];
#pragma unroll
            for (int j = 0; j < 4; j++) { float2 v = bf2[j]; b4[j] = pk2(v.x, v.y); }
#pragma unroll
            for (int i = 0; i < 4; i++)
#pragma unroll
                for (int j = 0; j < 4; j++) acc2[i][j] = f2fma(afp[i], b4[j], acc2[i][j]);
        }
    }
#pragma unroll
    for (int i = 0; i < 4; i++) {
        int px = px0 + pxg * 4 + i;
        float* zp = dXa + (size_t)px * 64 + og * 8;
        float2 r0 = upk(acc2[i][0]), r1 = upk(acc2[i][1]);
        float2 r2 = upk(acc2[i][2]), r3 = upk(acc2[i][3]);
        float4 v0, v1;
        v0.x = gelu(r0.x + bS[og*8+0]); v0.y = gelu(r0.y + bS[og*8+1]);
        v0.z = gelu(r1.x + bS[og*8+2]); v0.w = gelu(r1.y + bS[og*8+3]);
        v1.x = gelu(r2.x + bS[og*8+4]); v1.y = gelu(r2.y + bS[og*8+5]);
        v1.z = gelu(r3.x + bS[og*8+6]); v1.w = gelu(r3.y + bS[og*8+7]);
        ((float4*)zp)[0] = v0; ((float4*)zp)[1] = v1;
    }
}

// ---------------- MLP3 ----------------
__global__ void k_mlp3(const float* __restrict__ f3w, const float* __restrict__ f3b,
                       float* __restrict__ out) {
    __shared__ float w3[128];
    __shared__ float b3[2];
    int tid = threadIdx.x;
    if (tid < 128) w3[tid] = f3w[tid];
    if (tid < 2)   b3[tid] = f3b[tid];
    __syncthreads();
    int px = blockIdx.x * 256 + tid;
    const float4* zp = (const float4*)(dXa + (size_t)px * 64);
    float a0 = b3[0], a1 = b3[1];
#pragma unroll
    for (int i = 0; i < 16; i++) {
        float4 z = zp[i];
        a0 += z.x * w3[4*i] + z.y * w3[4*i+1] + z.z * w3[4*i+2] + z.w * w3[4*i+3];
        a1 += z.x * w3[64+4*i] + z.y * w3[64+4*i+1] + z.z * w3[64+4*i+2] + z.w * w3[64+4*i+3];
    }
    ((float2*)out)[px] = make_float2(a0, a1);
}

// ---------------- launch ----------------
extern "C" void kernel_launch(void* const* d_in, const int* in_sizes, int n_in,
                              void* d_out, int out_size) {
    const float* inp   = (const float*)d_in[0];
    const float* ext   = (const float*)d_in[1];
    const float* enc_w = (const float*)d_in[2];
    const float* enc_b = (const float*)d_in[3];
    const float* w1r   = (const float*)d_in[4];
    const float* w1i   = (const float*)d_in[5];
    const float* w2r   = (const float*)d_in[6];
    const float* w2i   = (const float*)d_in[7];
    const float* ws_w  = (const float*)d_in[8];
    const float* ws_b  = (const float*)d_in[9];
    const float* day   = (const float*)d_in[10];
    const float* hour  = (const float*)d_in[11];
    const float* e1w   = (const float*)d_in[12];
    const float* e1b   = (const float*)d_in[13];
    const float* e2w   = (const float*)d_in[14];
    const float* e2b   = (const float*)d_in[15];
    const float* tw    = (const float*)d_in[16];
    const float* tb    = (const float*)d_in[17];
    const float* f1w   = (const float*)d_in[18];
    const float* f1b   = (const float*)d_in[19];
    const float* f2w   = (const float*)d_in[20];
    const float* f2b   = (const float*)d_in[21];
    const float* f3w   = (const float*)d_in[22];
    const float* f3b   = (const float*)d_in[23];
    float* out = (float*)d_out;

    k_tab<<<60, 256>>>();
    k_wt<<<2048, 256>>>(w1r, w1i, w2r, w2i, tw);
    k_g1<<<32, 64>>>(ext, day, hour, e1w, e1b);
    k_g2<<<128, 256>>>(e2w, e2b);
    k_enc<<<4096, 256>>>(inp, enc_w, enc_b);

    float* bufA; float* bufB;
    cudaGetSymbolAddress((void**)&bufA, dXa);
    cudaGetSymbolAddress((void**)&bufB, dXb);

    float* src = bufA;
    float* dst = bufB;
    for (int l = 0; l < L_; l++) {
        k_fwd1<<<1024, 256>>>(src);
        k_fwd2<<<2048, 288>>>();
        k_mix<<<dim3(288, 4), 256>>>(l);
        k_inv1<<<2048, 128>>>();
        k_combine<<<4096, 256>>>(src, dst, ws_w + (size_t)l * 4096,
                                 ws_b + (size_t)l * 64, (l != L_ - 1) ? 1 : 0);
        float* t2 = src; src = dst; dst = t2;
    }
    k_conv<<<4096, 256>>>(src, dst, ext, tb);   // hfeat -> bufB [px][64]
    k_mlp1<<<8192, 256>>>(dst, f1w, f1b);       // -> dZ
    k_mlp2<<<8192, 256>>>(f2w, f2b);            // -> dXa [px][64]
    k_mlp3<<<4096, 256>>>(f3w, f3b, out);
}